// round 2
// baseline (speedup 1.0000x reference)
#include <cuda_runtime.h>
#include <cuda_bf16.h>

// INT4 symmetric grouped dequant, MLP=4 variant.
//   packed: TOTAL/2 int32 (one byte per int, two nibbles)
//   scale:  (OUT=4096, GROUPS=86) fp32, group size 128
//   out:    fp32, out[i] = (nibble - 8) * scale[i/128]
//
// Each thread: 4 block-strided int4 loads (front-batched -> MLP 4),
// then 8 float4 stores. 16B load covers 8 output floats; 8*16=128 so
// each int4 stays within one scale group: group = int4_index >> 4.

#define N_PACKED   22544384                 // TOTAL/2 int32s
#define N_INT4     (N_PACKED / 4)           // 5,636,096 int4 elements
#define THREADS    256
#define UNROLL     4
#define BLOCKS     (N_INT4 / (THREADS * UNROLL))   // 5504, exact

__global__ void __launch_bounds__(THREADS)
int4_dequant_kernel(const int4* __restrict__ packed,
                    const float* __restrict__ scale,
                    float4* __restrict__ out)
{
    const int base = blockIdx.x * (THREADS * UNROLL) + threadIdx.x;

    // Front-batched independent loads: MLP_p1 = 4
    int4 p[UNROLL];
#pragma unroll
    for (int k = 0; k < UNROLL; ++k)
        p[k] = packed[base + k * THREADS];

#pragma unroll
    for (int k = 0; k < UNROLL; ++k) {
        const int i = base + k * THREADS;     // int4 index
        const float s = __ldg(&scale[i >> 4]);

        float4 a, b;
        a.x = (float)(( p[k].x        & 15) - 8) * s;
        a.y = (float)(((p[k].x >> 4)  & 15) - 8) * s;
        a.z = (float)(( p[k].y        & 15) - 8) * s;
        a.w = (float)(((p[k].y >> 4)  & 15) - 8) * s;
        b.x = (float)(( p[k].z        & 15) - 8) * s;
        b.y = (float)(((p[k].z >> 4)  & 15) - 8) * s;
        b.z = (float)(( p[k].w        & 15) - 8) * s;
        b.w = (float)(((p[k].w >> 4)  & 15) - 8) * s;

        out[2 * i]     = a;
        out[2 * i + 1] = b;
    }
}

extern "C" void kernel_launch(void* const* d_in, const int* in_sizes, int n_in,
                              void* d_out, int out_size)
{
    const int4*  packed = (const int4*)d_in[0];
    const float* scale  = (const float*)d_in[1];
    float4*      out    = (float4*)d_out;

    int4_dequant_kernel<<<BLOCKS, THREADS>>>(packed, scale, out);
}

// round 3
// speedup vs baseline: 1.2393x; 1.2393x over previous
#include <cuda_runtime.h>
#include <cuda_bf16.h>

// INT4 symmetric grouped dequant — R1 shape + streaming cache hints.
//   packed: TOTAL/2 int32 (one byte each, two nibbles)
//   scale:  (4096, 86) fp32, group size 128
//   out:    fp32, out[i] = (nibble - 8) * scale[i/128]
//
// One int4 load (-> 8 codes) + two float4 stores per thread.
// 8*16 = 128 so each thread stays inside one scale group: group = t>>4.
// Streaming data (packed, out) uses evict-first (.cs) to keep the 126MB L2
// from thrashing on 270MB of use-once traffic; scale (1.4MB, 128x reuse)
// stays cached via __ldg.

#define N_PACKED   22544384            // TOTAL/2
#define N_THREADS  (N_PACKED / 4)      // 5,636,096 int4 loads
#define THREADS    256
#define BLOCKS     (N_THREADS / THREADS)   // 22,016 exact

__global__ void __launch_bounds__(THREADS)
int4_dequant_kernel(const int4* __restrict__ packed,
                    const float* __restrict__ scale,
                    float4* __restrict__ out)
{
    const int t = blockIdx.x * THREADS + threadIdx.x;

    const int4 p = __ldcs(&packed[t]);          // evict-first load
    const float s = __ldg(&scale[t >> 4]);      // cached, heavy reuse

    float4 a, b;
    a.x = (float)(( p.x       & 15) - 8) * s;
    a.y = (float)(((p.x >> 4) & 15) - 8) * s;
    a.z = (float)(( p.y       & 15) - 8) * s;
    a.w = (float)(((p.y >> 4) & 15) - 8) * s;
    b.x = (float)(( p.z       & 15) - 8) * s;
    b.y = (float)(((p.z >> 4) & 15) - 8) * s;
    b.z = (float)(( p.w       & 15) - 8) * s;
    b.w = (float)(((p.w >> 4) & 15) - 8) * s;

    __stcs(&out[2 * t],     a);                 // evict-first stores
    __stcs(&out[2 * t + 1], b);
}

extern "C" void kernel_launch(void* const* d_in, const int* in_sizes, int n_in,
                              void* d_out, int out_size)
{
    const int4*  packed = (const int4*)d_in[0];
    const float* scale  = (const float*)d_in[1];
    float4*      out    = (float4*)d_out;

    int4_dequant_kernel<<<BLOCKS, THREADS>>>(packed, scale, out);
}

// round 4
// speedup vs baseline: 1.2767x; 1.0302x over previous
#include <cuda_runtime.h>
#include <cuda_bf16.h>
#include <cstdint>

// INT4 symmetric grouped dequant — 256-bit ld/st (sm_100+ LDG.E.256/STG.E.256).
//   packed: TOTAL/2 int32 (one byte each, two nibbles: low = even elem, high = odd)
//   scale:  (4096, 86) fp32, group size 128
//   out:    fp32, out[i] = (nibble - 8) * scale[i/128]
//
// Each thread: one 32B v8 load (8 packed ints -> 16 codes) and two 32B v8
// stores (64B output). 16 codes * 8 threads = 128 = one scale group,
// so group = t >> 3 (uniform across 8 consecutive lanes).
// Streaming data uses evict-first (.cs); scale stays cached (128x reuse).

#define N_PACKED   22544384              // TOTAL/2 int32s
#define N_V8       (N_PACKED / 8)        // 2,818,048 threads
#define THREADS    256
#define BLOCKS     (N_V8 / THREADS)      // 11,008 exact

__global__ void __launch_bounds__(THREADS)
int4_dequant_kernel(const uint32_t* __restrict__ packed,
                    const float* __restrict__ scale,
                    float* __restrict__ out)
{
    const int t = blockIdx.x * THREADS + threadIdx.x;

    const float s = __ldg(&scale[t >> 3]);   // cached, heavy reuse

    uint32_t p[8];
    asm volatile(
        "ld.global.cs.v8.b32 {%0,%1,%2,%3,%4,%5,%6,%7}, [%8];"
        : "=r"(p[0]), "=r"(p[1]), "=r"(p[2]), "=r"(p[3]),
          "=r"(p[4]), "=r"(p[5]), "=r"(p[6]), "=r"(p[7])
        : "l"(packed + 8 * (size_t)t));

    float f[16];
#pragma unroll
    for (int j = 0; j < 8; ++j) {
        f[2 * j]     = (float)((int)(p[j] & 15u)        - 8) * s;
        f[2 * j + 1] = (float)((int)((p[j] >> 4) & 15u) - 8) * s;
    }

    float* o = out + 16 * (size_t)t;
    asm volatile(
        "st.global.cs.v8.f32 [%0], {%1,%2,%3,%4,%5,%6,%7,%8};"
        :: "l"(o),
           "f"(f[0]), "f"(f[1]), "f"(f[2]), "f"(f[3]),
           "f"(f[4]), "f"(f[5]), "f"(f[6]), "f"(f[7])
        : "memory");
    asm volatile(
        "st.global.cs.v8.f32 [%0], {%1,%2,%3,%4,%5,%6,%7,%8};"
        :: "l"(o + 8),
           "f"(f[8]),  "f"(f[9]),  "f"(f[10]), "f"(f[11]),
           "f"(f[12]), "f"(f[13]), "f"(f[14]), "f"(f[15])
        : "memory");
}

extern "C" void kernel_launch(void* const* d_in, const int* in_sizes, int n_in,
                              void* d_out, int out_size)
{
    const uint32_t* packed = (const uint32_t*)d_in[0];
    const float*    scale  = (const float*)d_in[1];
    float*          out    = (float*)d_out;

    int4_dequant_kernel<<<BLOCKS, THREADS>>>(packed, scale, out);
}